// round 1
// baseline (speedup 1.0000x reference)
#include <cuda_runtime.h>

#define UU 200000
#define NN 50000
#define EE 1600000

// Scratch (static __device__ arrays; allocation APIs are forbidden)
__device__ float g_P[(size_t)UU * 64];   // u2e @ W1[:64]
__device__ float g_Q[(size_t)NN * 64];   // u2e[nodes] @ W1[64:] + b1
__device__ float g_ex[EE];               // exp(logit) per edge
__device__ int   g_rs[NN + 1];           // row_start per node (seg_ids sorted)

// ---- packed f32x2 helpers (2x fp32 FMA per instruction on sm_103a) ----
__device__ __forceinline__ unsigned long long pack2(float a, float b) {
    unsigned long long r;
    asm("mov.b64 %0, {%1, %2};" : "=l"(r) : "f"(a), "f"(b));
    return r;
}
__device__ __forceinline__ void unpack2(unsigned long long v, float& a, float& b) {
    asm("mov.b64 {%0, %1}, %2;" : "=f"(a), "=f"(b) : "l"(v));
}
__device__ __forceinline__ void ffma2(unsigned long long& d,
                                      unsigned long long a, unsigned long long b) {
    asm("fma.rn.f32x2 %0, %1, %2, %0;" : "+l"(d) : "l"(a), "l"(b));
}

// ============================================================
// rowgemm64: out[r] = src[gather?gth[r]:r] @ W(64x64) (+ bias)
// 256 threads, 128 rows/block. smem: W (16KB) + X tile (128x68 padded)
// ============================================================
template <bool GATHER, bool BIAS>
__global__ void __launch_bounds__(256) rowgemm64(
    const float* __restrict__ src, const int* __restrict__ gth,
    const float* __restrict__ W, const float* __restrict__ bias,
    float* __restrict__ out, int rows)
{
    extern __shared__ float sm[];
    float* sW = sm;            // 4096 floats
    float* sX = sm + 4096;     // 128*68 floats

    int tid = threadIdx.x;
    for (int i = tid; i < 1024; i += 256)
        ((float4*)sW)[i] = ((const float4*)W)[i];

    int r0 = blockIdx.x * 128;
    for (int i = tid; i < 2048; i += 256) {
        int rl = i >> 4, j4 = i & 15;
        int r = r0 + rl;
        float4 v = make_float4(0.f, 0.f, 0.f, 0.f);
        if (r < rows) {
            long s = GATHER ? (long)__ldg(gth + r) : (long)r;
            v = __ldg((const float4*)(src + s * 64) + j4);
        }
        *(float4*)(sX + rl * 68 + j4 * 4) = v;
    }
    __syncthreads();

    int tx = tid & 15, ty = tid >> 4;
    unsigned long long acc[8][2];
#pragma unroll
    for (int i = 0; i < 8; i++) { acc[i][0] = 0ull; acc[i][1] = 0ull; }

#pragma unroll 8
    for (int k = 0; k < 64; k++) {
        ulonglong2 wv = *(const ulonglong2*)(sW + k * 64 + tx * 4);
#pragma unroll
        for (int i = 0; i < 8; i++) {
            float h = sX[(ty + i * 16) * 68 + k];
            unsigned long long hh = pack2(h, h);
            ffma2(acc[i][0], hh, wv.x);
            ffma2(acc[i][1], hh, wv.y);
        }
    }

    float4 bv = make_float4(0.f, 0.f, 0.f, 0.f);
    if (BIAS) bv = *(const float4*)(bias + tx * 4);
#pragma unroll
    for (int i = 0; i < 8; i++) {
        int r = r0 + ty + i * 16;
        if (r < rows) {
            float4 o;
            unpack2(acc[i][0], o.x, o.y);
            unpack2(acc[i][1], o.z, o.w);
            o.x += bv.x; o.y += bv.y; o.z += bv.z; o.w += bv.w;
            *(float4*)(out + (size_t)r * 64 + tx * 4) = o;
        }
    }
}

// ============================================================
// edge_mlp: per edge  h1 = relu(P[nb]+Q[sg]);
//           h2 = relu(h1@W2 + b2);  ex = exp(h2.w3 + b3)
// 256 threads, 128 edges/block (EE % 128 == 0).
// ============================================================
__global__ void __launch_bounds__(256) edge_mlp(
    const int* __restrict__ neigh, const int* __restrict__ seg,
    const float* __restrict__ W2, const float* __restrict__ b2,
    const float* __restrict__ w3, const float* __restrict__ b3)
{
    extern __shared__ float sm[];
    float* sW = sm;                       // 4096 floats
    float* sH = sm + 4096;                // 128*68 floats
    int*   sIdx = (int*)(sm + 4096 + 128 * 68); // 256 ints

    int tid = threadIdx.x;
    for (int i = tid; i < 1024; i += 256)
        ((float4*)sW)[i] = ((const float4*)W2)[i];

    int e0 = blockIdx.x * 128;
    if (tid < 128) {
        sIdx[tid]       = __ldg(neigh + e0 + tid);
        sIdx[128 + tid] = __ldg(seg   + e0 + tid);
    }
    __syncthreads();

    for (int i = tid; i < 2048; i += 256) {
        int el = i >> 4, j4 = i & 15;
        float4 p = __ldg((const float4*)(g_P + (size_t)sIdx[el]       * 64) + j4);
        float4 q = __ldg((const float4*)(g_Q + (size_t)sIdx[128 + el] * 64) + j4);
        float4 h;
        h.x = fmaxf(p.x + q.x, 0.f);
        h.y = fmaxf(p.y + q.y, 0.f);
        h.z = fmaxf(p.z + q.z, 0.f);
        h.w = fmaxf(p.w + q.w, 0.f);
        *(float4*)(sH + el * 68 + j4 * 4) = h;
    }
    __syncthreads();

    int tx = tid & 15, ty = tid >> 4;
    unsigned long long acc[8][2];
#pragma unroll
    for (int i = 0; i < 8; i++) { acc[i][0] = 0ull; acc[i][1] = 0ull; }

#pragma unroll 8
    for (int k = 0; k < 64; k++) {
        ulonglong2 wv = *(const ulonglong2*)(sW + k * 64 + tx * 4);
#pragma unroll
        for (int i = 0; i < 8; i++) {
            float h = sH[(ty + i * 16) * 68 + k];
            unsigned long long hh = pack2(h, h);
            ffma2(acc[i][0], hh, wv.x);
            ffma2(acc[i][1], hh, wv.y);
        }
    }

    float4 bv  = __ldg((const float4*)b2 + tx);
    float4 w3v = __ldg((const float4*)w3 + tx);
    float  b3v = __ldg(b3);
#pragma unroll
    for (int i = 0; i < 8; i++) {
        float a0, a1, a2, a3;
        unpack2(acc[i][0], a0, a1);
        unpack2(acc[i][1], a2, a3);
        float part = fmaxf(a0 + bv.x, 0.f) * w3v.x
                   + fmaxf(a1 + bv.y, 0.f) * w3v.y
                   + fmaxf(a2 + bv.z, 0.f) * w3v.z
                   + fmaxf(a3 + bv.w, 0.f) * w3v.w;
        // reduce over the 16 tx lanes (same half-warp: lane = (ty&1)*16 + tx)
        part += __shfl_xor_sync(0xffffffffu, part, 1);
        part += __shfl_xor_sync(0xffffffffu, part, 2);
        part += __shfl_xor_sync(0xffffffffu, part, 4);
        part += __shfl_xor_sync(0xffffffffu, part, 8);
        if (tx == 0)
            g_ex[e0 + ty + i * 16] = expf(part + b3v);
    }
}

// ============================================================
// rowptr: binary search for first edge of each node (seg sorted)
// ============================================================
__global__ void rowptr_k(const int* __restrict__ seg)
{
    int n = blockIdx.x * blockDim.x + threadIdx.x;
    if (n > NN) return;
    if (n == NN) { g_rs[NN] = EE; return; }
    int lo = 0, hi = EE;
    while (lo < hi) {
        int mid = (lo + hi) >> 1;
        if (__ldg(seg + mid) < n) lo = mid + 1; else hi = mid;
    }
    g_rs[n] = lo;
}

// ============================================================
// agg: one warp per node — softmax denom + weighted neighbor sum.
// Each lane owns 2 of the 64 dims.
// ============================================================
__global__ void __launch_bounds__(256) agg_k(
    const int* __restrict__ nodes, const int* __restrict__ neigh,
    const float* __restrict__ u2e, float* __restrict__ out)
{
    int w = (blockIdx.x * 256 + threadIdx.x) >> 5;
    int lane = threadIdx.x & 31;
    if (w >= NN) return;

    int s = g_rs[w], t = g_rs[w + 1];
    if (s == t) {  // no neighbors: fall back to own embedding
        int u = __ldg(nodes + w);
        float2 v = __ldg((const float2*)(u2e + (size_t)u * 64) + lane);
        *((float2*)(out + (size_t)w * 64) + lane) = v;
        return;
    }

    float d = 0.f;
    for (int e = s + lane; e < t; e += 32) d += __ldg(g_ex + e);
#pragma unroll
    for (int m = 16; m; m >>= 1) d += __shfl_xor_sync(0xffffffffu, d, m);
    float inv = 1.f / d;

    float ax = 0.f, ay = 0.f;
    int e = s;
    for (; e + 4 <= t; e += 4) {
        int n0 = __ldg(neigh + e),     n1 = __ldg(neigh + e + 1);
        int n2 = __ldg(neigh + e + 2), n3 = __ldg(neigh + e + 3);
        float w0 = __ldg(g_ex + e)     * inv, w1 = __ldg(g_ex + e + 1) * inv;
        float w2 = __ldg(g_ex + e + 2) * inv, w3 = __ldg(g_ex + e + 3) * inv;
        float2 v0 = __ldg((const float2*)(u2e + (size_t)n0 * 64) + lane);
        float2 v1 = __ldg((const float2*)(u2e + (size_t)n1 * 64) + lane);
        float2 v2 = __ldg((const float2*)(u2e + (size_t)n2 * 64) + lane);
        float2 v3 = __ldg((const float2*)(u2e + (size_t)n3 * 64) + lane);
        ax = fmaf(w0, v0.x, fmaf(w1, v1.x, fmaf(w2, v2.x, fmaf(w3, v3.x, ax))));
        ay = fmaf(w0, v0.y, fmaf(w1, v1.y, fmaf(w2, v2.y, fmaf(w3, v3.y, ay))));
    }
    for (; e < t; e++) {
        int n0 = __ldg(neigh + e);
        float w0 = __ldg(g_ex + e) * inv;
        float2 v0 = __ldg((const float2*)(u2e + (size_t)n0 * 64) + lane);
        ax = fmaf(w0, v0.x, ax);
        ay = fmaf(w0, v0.y, ay);
    }
    float2 o; o.x = ax; o.y = ay;
    *((float2*)(out + (size_t)w * 64) + lane) = o;
}

// ============================================================
extern "C" void kernel_launch(void* const* d_in, const int* in_sizes, int n_in,
                              void* d_out, int out_size)
{
    const int*   nodes = (const int*)d_in[0];
    const int*   neigh = (const int*)d_in[1];
    const int*   seg   = (const int*)d_in[2];
    const float* u2e   = (const float*)d_in[3];
    const float* W1    = (const float*)d_in[4];
    const float* b1    = (const float*)d_in[5];
    const float* W2    = (const float*)d_in[6];
    const float* b2    = (const float*)d_in[7];
    const float* w3    = (const float*)d_in[8];
    const float* b3    = (const float*)d_in[9];
    float* out = (float*)d_out;

    float *dP, *dQ;
    cudaGetSymbolAddress((void**)&dP, g_P);
    cudaGetSymbolAddress((void**)&dQ, g_Q);

    const int SMEM = (4096 + 128 * 68) * 4 + 1024;  // 52224 bytes
    cudaFuncSetAttribute(rowgemm64<false, false>,
                         cudaFuncAttributeMaxDynamicSharedMemorySize, SMEM);
    cudaFuncSetAttribute(rowgemm64<true, true>,
                         cudaFuncAttributeMaxDynamicSharedMemorySize, SMEM);
    cudaFuncSetAttribute(edge_mlp,
                         cudaFuncAttributeMaxDynamicSharedMemorySize, SMEM);

    // P = u2e @ W1[:64]          (identity rows, no bias)
    rowgemm64<false, false><<<(UU + 127) / 128, 256, SMEM>>>(
        u2e, nullptr, W1, nullptr, dP, UU);
    // Q = u2e[nodes] @ W1[64:] + b1
    rowgemm64<true, true><<<(NN + 127) / 128, 256, SMEM>>>(
        u2e, nodes, W1 + 64 * 64, b1, dQ, NN);
    // row_start per node
    rowptr_k<<<(NN + 1 + 255) / 256, 256>>>(seg);
    // per-edge MLP -> exp(logit)
    edge_mlp<<<EE / 128, 256, SMEM>>>(neigh, seg, W2, b2, w3, b3);
    // segment softmax + weighted aggregation (+ zero-neighbor fallback)
    agg_k<<<(NN * 32 + 255) / 256, 256>>>(nodes, neigh, u2e, out);
}

// round 2
// speedup vs baseline: 1.1075x; 1.1075x over previous
#include <cuda_runtime.h>

#define UU 200000
#define NN 50000
#define EE 1600000

// Scratch (static __device__ arrays; allocation APIs are forbidden)
__device__ float g_P[(size_t)UU * 64];   // u2e @ W1[:64]
__device__ float g_Q[(size_t)NN * 64];   // u2e[nodes] @ W1[64:] + b1
__device__ float g_ex[EE];               // exp(logit) per edge
__device__ int   g_rs[NN + 1];           // row_start per node (seg_ids sorted)

// ---- packed f32x2 helpers (2x fp32 FMA per instruction on sm_103a) ----
__device__ __forceinline__ unsigned long long pack2(float a, float b) {
    unsigned long long r;
    asm("mov.b64 %0, {%1, %2};" : "=l"(r) : "f"(a), "f"(b));
    return r;
}
__device__ __forceinline__ void unpack2(unsigned long long v, float& a, float& b) {
    asm("mov.b64 {%0, %1}, %2;" : "=f"(a), "=f"(b) : "l"(v));
}
__device__ __forceinline__ void ffma2(unsigned long long& d,
                                      unsigned long long a, unsigned long long b) {
    asm("fma.rn.f32x2 %0, %1, %2, %0;" : "+l"(d) : "l"(a), "l"(b));
}

// Core 128x64x64 tile GEMM: acc (8 rows x 4 cols per thread, f32x2 packed).
// k vectorized by 4: float4 h loads over k, 4x LDS.128 W rows.
__device__ __forceinline__ void gemm_tile_64(
    const float* __restrict__ sW, const float* __restrict__ sH,
    int tx, int ty, unsigned long long (&acc)[8][2])
{
#pragma unroll
    for (int kc = 0; kc < 64; kc += 4) {
        float4 h4[8];
#pragma unroll
        for (int i = 0; i < 8; i++)
            h4[i] = *(const float4*)(sH + (ty + i * 16) * 68 + kc);
        ulonglong2 wv[4];
#pragma unroll
        for (int kk = 0; kk < 4; kk++)
            wv[kk] = *(const ulonglong2*)(sW + (kc + kk) * 64 + tx * 4);
#pragma unroll
        for (int i = 0; i < 8; i++) {
            unsigned long long h0 = pack2(h4[i].x, h4[i].x);
            ffma2(acc[i][0], h0, wv[0].x); ffma2(acc[i][1], h0, wv[0].y);
            unsigned long long h1 = pack2(h4[i].y, h4[i].y);
            ffma2(acc[i][0], h1, wv[1].x); ffma2(acc[i][1], h1, wv[1].y);
            unsigned long long h2 = pack2(h4[i].z, h4[i].z);
            ffma2(acc[i][0], h2, wv[2].x); ffma2(acc[i][1], h2, wv[2].y);
            unsigned long long h3 = pack2(h4[i].w, h4[i].w);
            ffma2(acc[i][0], h3, wv[3].x); ffma2(acc[i][1], h3, wv[3].y);
        }
    }
}

// ============================================================
// rowgemm64: out[r] = src[gather?gth[r]:r] @ W(64x64) (+ bias)
// 256 threads, 128 rows/block. smem: W (16KB) + X tile (128x68 padded)
// ============================================================
template <bool GATHER, bool BIAS>
__global__ void __launch_bounds__(256, 3) rowgemm64(
    const float* __restrict__ src, const int* __restrict__ gth,
    const float* __restrict__ W, const float* __restrict__ bias,
    float* __restrict__ out, int rows)
{
    extern __shared__ float sm[];
    float* sW = sm;            // 4096 floats
    float* sX = sm + 4096;     // 128*68 floats

    int tid = threadIdx.x;
    for (int i = tid; i < 1024; i += 256)
        ((float4*)sW)[i] = ((const float4*)W)[i];

    int r0 = blockIdx.x * 128;
    for (int i = tid; i < 2048; i += 256) {
        int rl = i >> 4, j4 = i & 15;
        int r = r0 + rl;
        float4 v = make_float4(0.f, 0.f, 0.f, 0.f);
        if (r < rows) {
            long s = GATHER ? (long)__ldg(gth + r) : (long)r;
            v = __ldg((const float4*)(src + s * 64) + j4);
        }
        *(float4*)(sX + rl * 68 + j4 * 4) = v;
    }
    __syncthreads();

    int tx = tid & 15, ty = tid >> 4;
    unsigned long long acc[8][2];
#pragma unroll
    for (int i = 0; i < 8; i++) { acc[i][0] = 0ull; acc[i][1] = 0ull; }

    gemm_tile_64(sW, sX, tx, ty, acc);

    float4 bv = make_float4(0.f, 0.f, 0.f, 0.f);
    if (BIAS) bv = *(const float4*)(bias + tx * 4);
#pragma unroll
    for (int i = 0; i < 8; i++) {
        int r = r0 + ty + i * 16;
        if (r < rows) {
            float4 o;
            unpack2(acc[i][0], o.x, o.y);
            unpack2(acc[i][1], o.z, o.w);
            o.x += bv.x; o.y += bv.y; o.z += bv.z; o.w += bv.w;
            *(float4*)(out + (size_t)r * 64 + tx * 4) = o;
        }
    }
}

// ============================================================
// edge_mlp: per edge  h1 = relu(P[nb]+Q[sg]);
//           h2 = relu(h1@W2 + b2);  ex = exp(h2.w3 + b3)
// 256 threads, 128 edges/block (EE % 128 == 0).
// ============================================================
__global__ void __launch_bounds__(256, 3) edge_mlp(
    const int* __restrict__ neigh, const int* __restrict__ seg,
    const float* __restrict__ W2, const float* __restrict__ b2,
    const float* __restrict__ w3, const float* __restrict__ b3)
{
    extern __shared__ float sm[];
    float* sW = sm;                       // 4096 floats
    float* sH = sm + 4096;                // 128*68 floats
    int*   sIdx = (int*)(sm + 4096 + 128 * 68); // 256 ints

    int tid = threadIdx.x;
    for (int i = tid; i < 1024; i += 256)
        ((float4*)sW)[i] = ((const float4*)W2)[i];

    int e0 = blockIdx.x * 128;
    if (tid < 128) {
        sIdx[tid]       = __ldg(neigh + e0 + tid);
        sIdx[128 + tid] = __ldg(seg   + e0 + tid);
    }
    __syncthreads();

    for (int i = tid; i < 2048; i += 256) {
        int el = i >> 4, j4 = i & 15;
        float4 p = __ldg((const float4*)(g_P + (size_t)sIdx[el]       * 64) + j4);
        float4 q = __ldg((const float4*)(g_Q + (size_t)sIdx[128 + el] * 64) + j4);
        float4 h;
        h.x = fmaxf(p.x + q.x, 0.f);
        h.y = fmaxf(p.y + q.y, 0.f);
        h.z = fmaxf(p.z + q.z, 0.f);
        h.w = fmaxf(p.w + q.w, 0.f);
        *(float4*)(sH + el * 68 + j4 * 4) = h;
    }
    __syncthreads();

    int tx = tid & 15, ty = tid >> 4;
    unsigned long long acc[8][2];
#pragma unroll
    for (int i = 0; i < 8; i++) { acc[i][0] = 0ull; acc[i][1] = 0ull; }

    gemm_tile_64(sW, sH, tx, ty, acc);

    float4 bv  = __ldg((const float4*)b2 + tx);
    float4 w3v = __ldg((const float4*)w3 + tx);
    float  b3v = __ldg(b3);
#pragma unroll
    for (int i = 0; i < 8; i++) {
        float a0, a1, a2, a3;
        unpack2(acc[i][0], a0, a1);
        unpack2(acc[i][1], a2, a3);
        float part = fmaxf(a0 + bv.x, 0.f) * w3v.x
                   + fmaxf(a1 + bv.y, 0.f) * w3v.y
                   + fmaxf(a2 + bv.z, 0.f) * w3v.z
                   + fmaxf(a3 + bv.w, 0.f) * w3v.w;
        // reduce over the 16 tx lanes (same half-warp: lane = (ty&1)*16 + tx)
        part += __shfl_xor_sync(0xffffffffu, part, 1);
        part += __shfl_xor_sync(0xffffffffu, part, 2);
        part += __shfl_xor_sync(0xffffffffu, part, 4);
        part += __shfl_xor_sync(0xffffffffu, part, 8);
        if (tx == 0)
            g_ex[e0 + ty + i * 16] = expf(part + b3v);
    }
}

// ============================================================
// rowptr: binary search for first edge of each node (seg sorted)
// ============================================================
__global__ void rowptr_k(const int* __restrict__ seg)
{
    int n = blockIdx.x * blockDim.x + threadIdx.x;
    if (n > NN) return;
    if (n == NN) { g_rs[NN] = EE; return; }
    int lo = 0, hi = EE;
    while (lo < hi) {
        int mid = (lo + hi) >> 1;
        if (__ldg(seg + mid) < n) lo = mid + 1; else hi = mid;
    }
    g_rs[n] = lo;
}

// ============================================================
// agg: one warp per node — softmax denom + weighted neighbor sum.
// Each lane owns 2 of the 64 dims.
// ============================================================
__global__ void __launch_bounds__(256) agg_k(
    const int* __restrict__ nodes, const int* __restrict__ neigh,
    const float* __restrict__ u2e, float* __restrict__ out)
{
    int w = (blockIdx.x * 256 + threadIdx.x) >> 5;
    int lane = threadIdx.x & 31;
    if (w >= NN) return;

    int s = g_rs[w], t = g_rs[w + 1];
    if (s == t) {  // no neighbors: fall back to own embedding
        int u = __ldg(nodes + w);
        float2 v = __ldg((const float2*)(u2e + (size_t)u * 64) + lane);
        *((float2*)(out + (size_t)w * 64) + lane) = v;
        return;
    }

    float d = 0.f;
    for (int e = s + lane; e < t; e += 32) d += __ldg(g_ex + e);
#pragma unroll
    for (int m = 16; m; m >>= 1) d += __shfl_xor_sync(0xffffffffu, d, m);
    float inv = 1.f / d;

    float ax = 0.f, ay = 0.f;
    int e = s;
    for (; e + 4 <= t; e += 4) {
        int n0 = __ldg(neigh + e),     n1 = __ldg(neigh + e + 1);
        int n2 = __ldg(neigh + e + 2), n3 = __ldg(neigh + e + 3);
        float w0 = __ldg(g_ex + e)     * inv, w1 = __ldg(g_ex + e + 1) * inv;
        float w2 = __ldg(g_ex + e + 2) * inv, w3 = __ldg(g_ex + e + 3) * inv;
        float2 v0 = __ldg((const float2*)(u2e + (size_t)n0 * 64) + lane);
        float2 v1 = __ldg((const float2*)(u2e + (size_t)n1 * 64) + lane);
        float2 v2 = __ldg((const float2*)(u2e + (size_t)n2 * 64) + lane);
        float2 v3 = __ldg((const float2*)(u2e + (size_t)n3 * 64) + lane);
        ax = fmaf(w0, v0.x, fmaf(w1, v1.x, fmaf(w2, v2.x, fmaf(w3, v3.x, ax))));
        ay = fmaf(w0, v0.y, fmaf(w1, v1.y, fmaf(w2, v2.y, fmaf(w3, v3.y, ay))));
    }
    for (; e < t; e++) {
        int n0 = __ldg(neigh + e);
        float w0 = __ldg(g_ex + e) * inv;
        float2 v0 = __ldg((const float2*)(u2e + (size_t)n0 * 64) + lane);
        ax = fmaf(w0, v0.x, ax);
        ay = fmaf(w0, v0.y, ay);
    }
    float2 o; o.x = ax; o.y = ay;
    *((float2*)(out + (size_t)w * 64) + lane) = o;
}

// ============================================================
extern "C" void kernel_launch(void* const* d_in, const int* in_sizes, int n_in,
                              void* d_out, int out_size)
{
    const int*   nodes = (const int*)d_in[0];
    const int*   neigh = (const int*)d_in[1];
    const int*   seg   = (const int*)d_in[2];
    const float* u2e   = (const float*)d_in[3];
    const float* W1    = (const float*)d_in[4];
    const float* b1    = (const float*)d_in[5];
    const float* W2    = (const float*)d_in[6];
    const float* b2    = (const float*)d_in[7];
    const float* w3    = (const float*)d_in[8];
    const float* b3    = (const float*)d_in[9];
    float* out = (float*)d_out;

    float *dP, *dQ;
    cudaGetSymbolAddress((void**)&dP, g_P);
    cudaGetSymbolAddress((void**)&dQ, g_Q);

    const int SMEM = (4096 + 128 * 68) * 4 + 1024;  // 52224 bytes
    cudaFuncSetAttribute(rowgemm64<false, false>,
                         cudaFuncAttributeMaxDynamicSharedMemorySize, SMEM);
    cudaFuncSetAttribute(rowgemm64<true, true>,
                         cudaFuncAttributeMaxDynamicSharedMemorySize, SMEM);
    cudaFuncSetAttribute(edge_mlp,
                         cudaFuncAttributeMaxDynamicSharedMemorySize, SMEM);

    // P = u2e @ W1[:64]          (identity rows, no bias)
    rowgemm64<false, false><<<(UU + 127) / 128, 256, SMEM>>>(
        u2e, nullptr, W1, nullptr, dP, UU);
    // Q = u2e[nodes] @ W1[64:] + b1
    rowgemm64<true, true><<<(NN + 127) / 128, 256, SMEM>>>(
        u2e, nodes, W1 + 64 * 64, b1, dQ, NN);
    // row_start per node
    rowptr_k<<<(NN + 1 + 255) / 256, 256>>>(seg);
    // per-edge MLP -> exp(logit)
    edge_mlp<<<EE / 128, 256, SMEM>>>(neigh, seg, W2, b2, w3, b3);
    // segment softmax + weighted aggregation (+ zero-neighbor fallback)
    agg_k<<<(NN * 32 + 255) / 256, 256>>>(nodes, neigh, u2e, out);
}

// round 5
// speedup vs baseline: 1.3769x; 1.2432x over previous
#include <cuda_runtime.h>
#include <cuda_bf16.h>
#include <cstdint>

#define UU 200000
#define NN 50000
#define EE 1600000

// Scratch (static __device__ arrays; allocation APIs are forbidden)
__device__ float g_P[(size_t)UU * 64];   // u2e @ W1[:64]
__device__ float g_Q[(size_t)NN * 64];   // u2e[nodes] @ W1[64:] + b1
__device__ float g_ex[EE];               // exp(logit) per edge
__device__ int   g_rs[NN + 1];           // row_start per node (seg_ids sorted)
// W2 (as B = W2[k][n]) pre-packed in m16n8k16 B-fragment order, bf16 hi/lo.
// Layout: word[(nt*32 + lane)*8 + w], w = ks*2 + reg  (reg0: k=ks*16+tg*2, reg1: +8)
__device__ uint32_t g_Bfhi[2048];
__device__ uint32_t g_Bflo[2048];

// ================= helpers =================
__device__ __forceinline__ unsigned short f2bf(float x) {
    __nv_bfloat16 b = __float2bfloat16_rn(x);
    return *reinterpret_cast<unsigned short*>(&b);
}
__device__ __forceinline__ float bf2f(unsigned short s) {
    __nv_bfloat16 b = *reinterpret_cast<__nv_bfloat16*>(&s);
    return __bfloat162float(b);
}
__device__ __forceinline__ uint32_t bfpack(float x, float y) {
    return (uint32_t)f2bf(x) | ((uint32_t)f2bf(y) << 16);
}

// D(16x8,f32) += A(16x16,bf16,row) x B(16x8,bf16,col)  — HMMA fallback path
__device__ __forceinline__ void mma_bf16(float (&c)[4],
    uint32_t a0, uint32_t a1, uint32_t a2, uint32_t a3,
    uint32_t b0, uint32_t b1)
{
    asm volatile(
        "mma.sync.aligned.m16n8k16.row.col.f32.bf16.bf16.f32 "
        "{%0,%1,%2,%3}, {%4,%5,%6,%7}, {%8,%9}, {%0,%1,%2,%3};"
        : "+f"(c[0]), "+f"(c[1]), "+f"(c[2]), "+f"(c[3])
        : "r"(a0), "r"(a1), "r"(a2), "r"(a3), "r"(b0), "r"(b1));
}

// ---- packed f32x2 helpers (rowgemm kernels) ----
__device__ __forceinline__ unsigned long long pack2(float a, float b) {
    unsigned long long r;
    asm("mov.b64 %0, {%1, %2};" : "=l"(r) : "f"(a), "f"(b));
    return r;
}
__device__ __forceinline__ void unpack2(unsigned long long v, float& a, float& b) {
    asm("mov.b64 {%0, %1}, %2;" : "=f"(a), "=f"(b) : "l"(v));
}
__device__ __forceinline__ void ffma2(unsigned long long& d,
                                      unsigned long long a, unsigned long long b) {
    asm("fma.rn.f32x2 %0, %1, %2, %0;" : "+l"(d) : "l"(a), "l"(b));
}

__device__ __forceinline__ void gemm_tile_64(
    const float* __restrict__ sW, const float* __restrict__ sH,
    int tx, int ty, unsigned long long (&acc)[8][2])
{
#pragma unroll
    for (int kc = 0; kc < 64; kc += 4) {
        float4 h4[8];
#pragma unroll
        for (int i = 0; i < 8; i++)
            h4[i] = *(const float4*)(sH + (ty + i * 16) * 68 + kc);
        ulonglong2 wv[4];
#pragma unroll
        for (int kk = 0; kk < 4; kk++)
            wv[kk] = *(const ulonglong2*)(sW + (kc + kk) * 64 + tx * 4);
#pragma unroll
        for (int i = 0; i < 8; i++) {
            unsigned long long h0 = pack2(h4[i].x, h4[i].x);
            ffma2(acc[i][0], h0, wv[0].x); ffma2(acc[i][1], h0, wv[0].y);
            unsigned long long h1 = pack2(h4[i].y, h4[i].y);
            ffma2(acc[i][0], h1, wv[1].x); ffma2(acc[i][1], h1, wv[1].y);
            unsigned long long h2 = pack2(h4[i].z, h4[i].z);
            ffma2(acc[i][0], h2, wv[2].x); ffma2(acc[i][1], h2, wv[2].y);
            unsigned long long h3 = pack2(h4[i].w, h4[i].w);
            ffma2(acc[i][0], h3, wv[3].x); ffma2(acc[i][1], h3, wv[3].y);
        }
    }
}

// ============================================================
// rowgemm64: out[r] = src[gather?gth[r]:r] @ W(64x64) (+ bias)
// ============================================================
template <bool GATHER, bool BIAS>
__global__ void __launch_bounds__(256, 3) rowgemm64(
    const float* __restrict__ src, const int* __restrict__ gth,
    const float* __restrict__ W, const float* __restrict__ bias,
    float* __restrict__ out, int rows)
{
    extern __shared__ float sm[];
    float* sW = sm;            // 4096 floats
    float* sX = sm + 4096;     // 128*68 floats

    int tid = threadIdx.x;
    for (int i = tid; i < 1024; i += 256)
        ((float4*)sW)[i] = ((const float4*)W)[i];

    int r0 = blockIdx.x * 128;
    for (int i = tid; i < 2048; i += 256) {
        int rl = i >> 4, j4 = i & 15;
        int r = r0 + rl;
        float4 v = make_float4(0.f, 0.f, 0.f, 0.f);
        if (r < rows) {
            long s = GATHER ? (long)__ldg(gth + r) : (long)r;
            v = __ldg((const float4*)(src + s * 64) + j4);
        }
        *(float4*)(sX + rl * 68 + j4 * 4) = v;
    }
    __syncthreads();

    int tx = tid & 15, ty = tid >> 4;
    unsigned long long acc[8][2];
#pragma unroll
    for (int i = 0; i < 8; i++) { acc[i][0] = 0ull; acc[i][1] = 0ull; }

    gemm_tile_64(sW, sX, tx, ty, acc);

    float4 bv = make_float4(0.f, 0.f, 0.f, 0.f);
    if (BIAS) bv = *(const float4*)(bias + tx * 4);
#pragma unroll
    for (int i = 0; i < 8; i++) {
        int r = r0 + ty + i * 16;
        if (r < rows) {
            float4 o;
            unpack2(acc[i][0], o.x, o.y);
            unpack2(acc[i][1], o.z, o.w);
            o.x += bv.x; o.y += bv.y; o.z += bv.z; o.w += bv.w;
            *(float4*)(out + (size_t)r * 64 + tx * 4) = o;
        }
    }
}

// ============================================================
// prep_w2: pack W2 into B-fragment order (bf16 hi/lo).
// For word index i: nt=i/256, L=(i/8)%32, w=i%8; ks=w>>1, reg=w&1;
// g=L>>2, tg=L&3; n=nt*8+g; k=ks*16+reg*8+tg*2; value pair (k, k+1) at col n.
// ============================================================
__global__ void prep_w2(const float* __restrict__ W2)
{
    int i = blockIdx.x * blockDim.x + threadIdx.x;
    if (i >= 2048) return;
    int nt = i >> 8, L = (i >> 3) & 31, w = i & 7;
    int ks = w >> 1, reg = w & 1;
    int g = L >> 2, tg = L & 3;
    int n = nt * 8 + g;
    int k = ks * 16 + reg * 8 + tg * 2;
    float v0 = __ldg(W2 + k * 64 + n);
    float v1 = __ldg(W2 + (k + 1) * 64 + n);
    unsigned short h0 = f2bf(v0), h1 = f2bf(v1);
    float r0 = v0 - bf2f(h0), r1 = v1 - bf2f(h1);
    g_Bfhi[i] = (uint32_t)h0 | ((uint32_t)h1 << 16);
    g_Bflo[i] = (uint32_t)f2bf(r0) | ((uint32_t)f2bf(r1) << 16);
}

// ============================================================
// edge_mlp_mma: per 128-edge tile
//   h = relu(P[nb]+Q[sg]) -> bf16 hi/lo tiles in smem (pitch 36 words/row)
//   D = Ah*Bh + Ah*Bl + Al*Bh via mma.sync (HMMA), fp32 accum
//   epilogue: relu(D+b2).w3, 4-lane reduce, exp -> g_ex
// 256 threads = 8 warps; warp w owns rows w*16..w*16+15.
// ============================================================
__global__ void __launch_bounds__(256) edge_mlp_mma(
    const int* __restrict__ neigh, const int* __restrict__ seg,
    const float* __restrict__ b2, const float* __restrict__ w3,
    const float* __restrict__ b3)
{
    __shared__ uint32_t sHhi[128 * 36];
    __shared__ uint32_t sHlo[128 * 36];
    __shared__ int sIdx[256];

    int tid = threadIdx.x;
    int wid = tid >> 5, lane = tid & 31;
    int g = lane >> 2, tg = lane & 3;
    int e0 = blockIdx.x * 128;

    if (tid < 128) {
        sIdx[tid]       = __ldg(neigh + e0 + tid);
        sIdx[128 + tid] = __ldg(seg   + e0 + tid);
    }
    __syncthreads();

    // gather + relu + hi/lo split; each iter covers one row's 8-k chunk
    for (int i = tid; i < 1024; i += 256) {
        int r = i >> 3, k8 = i & 7;
        const float4* Pr = (const float4*)(g_P + (size_t)sIdx[r] * 64) + k8 * 2;
        const float4* Qr = (const float4*)(g_Q + (size_t)sIdx[128 + r] * 64) + k8 * 2;
        float4 p0 = __ldg(Pr), p1 = __ldg(Pr + 1);
        float4 q0 = __ldg(Qr), q1 = __ldg(Qr + 1);
        float h[8];
        h[0] = fmaxf(p0.x + q0.x, 0.f); h[1] = fmaxf(p0.y + q0.y, 0.f);
        h[2] = fmaxf(p0.z + q0.z, 0.f); h[3] = fmaxf(p0.w + q0.w, 0.f);
        h[4] = fmaxf(p1.x + q1.x, 0.f); h[5] = fmaxf(p1.y + q1.y, 0.f);
        h[6] = fmaxf(p1.z + q1.z, 0.f); h[7] = fmaxf(p1.w + q1.w, 0.f);
        uint32_t hi[4], lo[4];
#pragma unroll
        for (int j = 0; j < 4; j++) {
            unsigned short a = f2bf(h[2 * j]), b = f2bf(h[2 * j + 1]);
            hi[j] = (uint32_t)a | ((uint32_t)b << 16);
            lo[j] = bfpack(h[2 * j] - bf2f(a), h[2 * j + 1] - bf2f(b));
        }
        int base = r * 36 + k8 * 4;
        *(uint4*)(sHhi + base) = make_uint4(hi[0], hi[1], hi[2], hi[3]);
        *(uint4*)(sHlo + base) = make_uint4(lo[0], lo[1], lo[2], lo[3]);
    }
    __syncthreads();

    // A fragments: rows rb+g / rb+g+8, word kpair = ks*8 + khalf*4 + tg
    int rb = wid * 16;
    uint32_t ahi[4][4], alo[4][4];
#pragma unroll
    for (int ks = 0; ks < 4; ks++) {
        int b0 = (rb + g) * 36 + ks * 8 + tg;
        int b1 = b0 + 8 * 36;
        ahi[ks][0] = sHhi[b0];     ahi[ks][1] = sHhi[b1];
        ahi[ks][2] = sHhi[b0 + 4]; ahi[ks][3] = sHhi[b1 + 4];
        alo[ks][0] = sHlo[b0];     alo[ks][1] = sHlo[b1];
        alo[ks][2] = sHlo[b0 + 4]; alo[ks][3] = sHlo[b1 + 4];
    }

    float acc[8][4];
#pragma unroll
    for (int nt = 0; nt < 8; nt++) {
        acc[nt][0] = acc[nt][1] = acc[nt][2] = acc[nt][3] = 0.f;
        const uint4* Bh = (const uint4*)(g_Bfhi + (nt * 32 + lane) * 8);
        const uint4* Bl = (const uint4*)(g_Bflo + (nt * 32 + lane) * 8);
        uint4 bh0 = __ldg(Bh), bh1 = __ldg(Bh + 1);
        uint4 bl0 = __ldg(Bl), bl1 = __ldg(Bl + 1);
        // ks0
        mma_bf16(acc[nt], ahi[0][0], ahi[0][1], ahi[0][2], ahi[0][3], bh0.x, bh0.y);
        mma_bf16(acc[nt], alo[0][0], alo[0][1], alo[0][2], alo[0][3], bh0.x, bh0.y);
        mma_bf16(acc[nt], ahi[0][0], ahi[0][1], ahi[0][2], ahi[0][3], bl0.x, bl0.y);
        // ks1
        mma_bf16(acc[nt], ahi[1][0], ahi[1][1], ahi[1][2], ahi[1][3], bh0.z, bh0.w);
        mma_bf16(acc[nt], alo[1][0], alo[1][1], alo[1][2], alo[1][3], bh0.z, bh0.w);
        mma_bf16(acc[nt], ahi[1][0], ahi[1][1], ahi[1][2], ahi[1][3], bl0.z, bl0.w);
        // ks2
        mma_bf16(acc[nt], ahi[2][0], ahi[2][1], ahi[2][2], ahi[2][3], bh1.x, bh1.y);
        mma_bf16(acc[nt], alo[2][0], alo[2][1], alo[2][2], alo[2][3], bh1.x, bh1.y);
        mma_bf16(acc[nt], ahi[2][0], ahi[2][1], ahi[2][2], ahi[2][3], bl1.x, bl1.y);
        // ks3
        mma_bf16(acc[nt], ahi[3][0], ahi[3][1], ahi[3][2], ahi[3][3], bh1.z, bh1.w);
        mma_bf16(acc[nt], alo[3][0], alo[3][1], alo[3][2], alo[3][3], bh1.z, bh1.w);
        mma_bf16(acc[nt], ahi[3][0], ahi[3][1], ahi[3][2], ahi[3][3], bl1.z, bl1.w);
    }

    // epilogue: rows rb+g (c0,c1) and rb+g+8 (c2,c3); cols nt*8 + tg*2 + {0,1}
    float s0 = 0.f, s1 = 0.f;
#pragma unroll
    for (int nt = 0; nt < 8; nt++) {
        int c0 = nt * 8 + tg * 2, c1 = c0 + 1;
        float bb0 = __ldg(b2 + c0), bb1 = __ldg(b2 + c1);
        float ww0 = __ldg(w3 + c0), ww1 = __ldg(w3 + c1);
        s0 += fmaxf(acc[nt][0] + bb0, 0.f) * ww0 + fmaxf(acc[nt][1] + bb1, 0.f) * ww1;
        s1 += fmaxf(acc[nt][2] + bb0, 0.f) * ww0 + fmaxf(acc[nt][3] + bb1, 0.f) * ww1;
    }
    s0 += __shfl_xor_sync(0xffffffffu, s0, 1);
    s0 += __shfl_xor_sync(0xffffffffu, s0, 2);
    s1 += __shfl_xor_sync(0xffffffffu, s1, 1);
    s1 += __shfl_xor_sync(0xffffffffu, s1, 2);
    if (tg == 0) {
        float b3v = __ldg(b3);
        g_ex[e0 + rb + g]     = expf(s0 + b3v);
        g_ex[e0 + rb + g + 8] = expf(s1 + b3v);
    }
}

// ============================================================
// rowptr: binary search for first edge of each node (seg sorted)
// ============================================================
__global__ void rowptr_k(const int* __restrict__ seg)
{
    int n = blockIdx.x * blockDim.x + threadIdx.x;
    if (n > NN) return;
    if (n == NN) { g_rs[NN] = EE; return; }
    int lo = 0, hi = EE;
    while (lo < hi) {
        int mid = (lo + hi) >> 1;
        if (__ldg(seg + mid) < n) lo = mid + 1; else hi = mid;
    }
    g_rs[n] = lo;
}

// ============================================================
// agg: one warp per node — softmax denom + weighted neighbor sum.
// ============================================================
__global__ void __launch_bounds__(256) agg_k(
    const int* __restrict__ nodes, const int* __restrict__ neigh,
    const float* __restrict__ u2e, float* __restrict__ out)
{
    int w = (blockIdx.x * 256 + threadIdx.x) >> 5;
    int lane = threadIdx.x & 31;
    if (w >= NN) return;

    int s = g_rs[w], t = g_rs[w + 1];
    if (s == t) {
        int u = __ldg(nodes + w);
        float2 v = __ldg((const float2*)(u2e + (size_t)u * 64) + lane);
        *((float2*)(out + (size_t)w * 64) + lane) = v;
        return;
    }

    float d = 0.f;
    for (int e = s + lane; e < t; e += 32) d += __ldg(g_ex + e);
#pragma unroll
    for (int m = 16; m; m >>= 1) d += __shfl_xor_sync(0xffffffffu, d, m);
    float inv = 1.f / d;

    float ax = 0.f, ay = 0.f;
    int e = s;
    for (; e + 4 <= t; e += 4) {
        int n0 = __ldg(neigh + e),     n1 = __ldg(neigh + e + 1);
        int n2 = __ldg(neigh + e + 2), n3 = __ldg(neigh + e + 3);
        float w0 = __ldg(g_ex + e)     * inv, w1 = __ldg(g_ex + e + 1) * inv;
        float w2 = __ldg(g_ex + e + 2) * inv, w3 = __ldg(g_ex + e + 3) * inv;
        float2 v0 = __ldg((const float2*)(u2e + (size_t)n0 * 64) + lane);
        float2 v1 = __ldg((const float2*)(u2e + (size_t)n1 * 64) + lane);
        float2 v2 = __ldg((const float2*)(u2e + (size_t)n2 * 64) + lane);
        float2 v3 = __ldg((const float2*)(u2e + (size_t)n3 * 64) + lane);
        ax = fmaf(w0, v0.x, fmaf(w1, v1.x, fmaf(w2, v2.x, fmaf(w3, v3.x, ax))));
        ay = fmaf(w0, v0.y, fmaf(w1, v1.y, fmaf(w2, v2.y, fmaf(w3, v3.y, ay))));
    }
    for (; e < t; e++) {
        int n0 = __ldg(neigh + e);
        float w0 = __ldg(g_ex + e) * inv;
        float2 v0 = __ldg((const float2*)(u2e + (size_t)n0 * 64) + lane);
        ax = fmaf(w0, v0.x, ax);
        ay = fmaf(w0, v0.y, ay);
    }
    float2 o; o.x = ax; o.y = ay;
    *((float2*)(out + (size_t)w * 64) + lane) = o;
}

// ============================================================
extern "C" void kernel_launch(void* const* d_in, const int* in_sizes, int n_in,
                              void* d_out, int out_size)
{
    const int*   nodes = (const int*)d_in[0];
    const int*   neigh = (const int*)d_in[1];
    const int*   seg   = (const int*)d_in[2];
    const float* u2e   = (const float*)d_in[3];
    const float* W1    = (const float*)d_in[4];
    const float* b1    = (const float*)d_in[5];
    const float* W2    = (const float*)d_in[6];
    const float* b2    = (const float*)d_in[7];
    const float* w3    = (const float*)d_in[8];
    const float* b3    = (const float*)d_in[9];
    float* out = (float*)d_out;

    float *dP, *dQ;
    cudaGetSymbolAddress((void**)&dP, g_P);
    cudaGetSymbolAddress((void**)&dQ, g_Q);

    const int SMEM = (4096 + 128 * 68) * 4 + 1024;  // 52224 bytes
    cudaFuncSetAttribute(rowgemm64<false, false>,
                         cudaFuncAttributeMaxDynamicSharedMemorySize, SMEM);
    cudaFuncSetAttribute(rowgemm64<true, true>,
                         cudaFuncAttributeMaxDynamicSharedMemorySize, SMEM);

    // P = u2e @ W1[:64]          (identity rows, no bias)
    rowgemm64<false, false><<<(UU + 127) / 128, 256, SMEM>>>(
        u2e, nullptr, W1, nullptr, dP, UU);
    // Q = u2e[nodes] @ W1[64:] + b1
    rowgemm64<true, true><<<(NN + 127) / 128, 256, SMEM>>>(
        u2e, nodes, W1 + 64 * 64, b1, dQ, NN);
    // W2 -> B-fragment order (bf16 hi/lo)
    prep_w2<<<8, 256>>>(W2);
    // row_start per node
    rowptr_k<<<(NN + 1 + 255) / 256, 256>>>(seg);
    // per-edge MLP -> exp(logit)  (HMMA via mma.sync)
    edge_mlp_mma<<<EE / 128, 256>>>(neigh, seg, b2, w3, b3);
    // segment softmax + weighted aggregation (+ zero-neighbor fallback)
    agg_k<<<(NN * 32 + 255) / 256, 256>>>(nodes, neigh, u2e, out);
}

// round 6
// speedup vs baseline: 1.5084x; 1.0955x over previous
#include <cuda_runtime.h>
#include <cuda_bf16.h>
#include <cstdint>

#define UU 200000
#define NN 50000
#define EE 1600000

// Scratch (static __device__ arrays; allocation APIs are forbidden)
__device__ float g_P[(size_t)UU * 64];   // u2e @ W1[:64]
__device__ float g_Q[(size_t)NN * 64];   // u2e[nodes] @ W1[64:] + b1
__device__ float g_ex[EE];               // exp(logit) per edge
// Weights pre-packed in m16n8k16 B-fragment order, bf16 hi/lo.
// word[(nt*32 + lane)*8 + w], w = ks*2 + reg (reg0: k=ks*16+tg*2, reg1: +8)
__device__ uint32_t g_Bfhi[2048],  g_Bflo[2048];   // W2
__device__ uint32_t g_BW1thi[2048], g_BW1tlo[2048]; // W1 top  (rows 0..63)
__device__ uint32_t g_BW1bhi[2048], g_BW1blo[2048]; // W1 bottom (rows 64..127)

// ================= helpers =================
__device__ __forceinline__ unsigned short f2bf(float x) {
    __nv_bfloat16 b = __float2bfloat16_rn(x);
    return *reinterpret_cast<unsigned short*>(&b);
}
__device__ __forceinline__ float bf2f(unsigned short s) {
    __nv_bfloat16 b = *reinterpret_cast<__nv_bfloat16*>(&s);
    return __bfloat162float(b);
}
__device__ __forceinline__ uint32_t bfpack(float x, float y) {
    return (uint32_t)f2bf(x) | ((uint32_t)f2bf(y) << 16);
}

// D(16x8,f32) += A(16x16,bf16,row) x B(16x8,bf16,col)  — HMMA fallback path
__device__ __forceinline__ void mma_bf16(float (&c)[4],
    uint32_t a0, uint32_t a1, uint32_t a2, uint32_t a3,
    uint32_t b0, uint32_t b1)
{
    asm volatile(
        "mma.sync.aligned.m16n8k16.row.col.f32.bf16.bf16.f32 "
        "{%0,%1,%2,%3}, {%4,%5,%6,%7}, {%8,%9}, {%0,%1,%2,%3};"
        : "+f"(c[0]), "+f"(c[1]), "+f"(c[2]), "+f"(c[3])
        : "r"(a0), "r"(a1), "r"(a2), "r"(a3), "r"(b0), "r"(b1));
}

// Run 12 hi/lo MMAs (Ah*Bh + Al*Bh + Ah*Bl) for one n-tile
__device__ __forceinline__ void mma_hilo_ntile(float (&acc)[4],
    const uint32_t (&ahi)[4][4], const uint32_t (&alo)[4][4],
    const uint32_t* __restrict__ Bhi, const uint32_t* __restrict__ Blo,
    int nt, int lane)
{
    const uint4* Bh = (const uint4*)(Bhi + (nt * 32 + lane) * 8);
    const uint4* Bl = (const uint4*)(Blo + (nt * 32 + lane) * 8);
    uint4 bh0 = __ldg(Bh), bh1 = __ldg(Bh + 1);
    uint4 bl0 = __ldg(Bl), bl1 = __ldg(Bl + 1);
    mma_bf16(acc, ahi[0][0], ahi[0][1], ahi[0][2], ahi[0][3], bh0.x, bh0.y);
    mma_bf16(acc, alo[0][0], alo[0][1], alo[0][2], alo[0][3], bh0.x, bh0.y);
    mma_bf16(acc, ahi[0][0], ahi[0][1], ahi[0][2], ahi[0][3], bl0.x, bl0.y);
    mma_bf16(acc, ahi[1][0], ahi[1][1], ahi[1][2], ahi[1][3], bh0.z, bh0.w);
    mma_bf16(acc, alo[1][0], alo[1][1], alo[1][2], alo[1][3], bh0.z, bh0.w);
    mma_bf16(acc, ahi[1][0], ahi[1][1], ahi[1][2], ahi[1][3], bl0.z, bl0.w);
    mma_bf16(acc, ahi[2][0], ahi[2][1], ahi[2][2], ahi[2][3], bh1.x, bh1.y);
    mma_bf16(acc, alo[2][0], alo[2][1], alo[2][2], alo[2][3], bh1.x, bh1.y);
    mma_bf16(acc, ahi[2][0], ahi[2][1], ahi[2][2], ahi[2][3], bl1.x, bl1.y);
    mma_bf16(acc, ahi[3][0], ahi[3][1], ahi[3][2], ahi[3][3], bh1.z, bh1.w);
    mma_bf16(acc, alo[3][0], alo[3][1], alo[3][2], alo[3][3], bh1.z, bh1.w);
    mma_bf16(acc, ahi[3][0], ahi[3][1], ahi[3][2], ahi[3][3], bl1.z, bl1.w);
}

// Load per-warp A fragments from pitch-36 smem tiles
__device__ __forceinline__ void load_afrag(
    const uint32_t* __restrict__ sHhi, const uint32_t* __restrict__ sHlo,
    int rb, int g, int tg, uint32_t (&ahi)[4][4], uint32_t (&alo)[4][4])
{
#pragma unroll
    for (int ks = 0; ks < 4; ks++) {
        int b0 = (rb + g) * 36 + ks * 8 + tg;
        int b1 = b0 + 8 * 36;
        ahi[ks][0] = sHhi[b0];     ahi[ks][1] = sHhi[b1];
        ahi[ks][2] = sHhi[b0 + 4]; ahi[ks][3] = sHhi[b1 + 4];
        alo[ks][0] = sHlo[b0];     alo[ks][1] = sHlo[b1];
        alo[ks][2] = sHlo[b0 + 4]; alo[ks][3] = sHlo[b1 + 4];
    }
}

// ============================================================
// prep_pack: pack a 64x64 k-major weight block into B-fragment order.
// ============================================================
__global__ void prep_pack(const float* __restrict__ W,
                          uint32_t* __restrict__ dhi, uint32_t* __restrict__ dlo)
{
    int i = blockIdx.x * blockDim.x + threadIdx.x;
    if (i >= 2048) return;
    int nt = i >> 8, L = (i >> 3) & 31, w = i & 7;
    int ks = w >> 1, reg = w & 1;
    int g = L >> 2, tg = L & 3;
    int n = nt * 8 + g;
    int k = ks * 16 + reg * 8 + tg * 2;
    float v0 = __ldg(W + k * 64 + n);
    float v1 = __ldg(W + (k + 1) * 64 + n);
    unsigned short h0 = f2bf(v0), h1 = f2bf(v1);
    dhi[i] = (uint32_t)h0 | ((uint32_t)h1 << 16);
    dlo[i] = bfpack(v0 - bf2f(h0), v1 - bf2f(h1));
}

// ============================================================
// rowgemm_mma: out[r] = src[gather?gth[r]:r] @ W(64x64) (+ bias)  via HMMA
// 256 threads = 8 warps; 128 rows/block.
// ============================================================
template <bool GATHER, bool BIAS>
__global__ void __launch_bounds__(256) rowgemm_mma(
    const float* __restrict__ src, const int* __restrict__ gth,
    const uint32_t* __restrict__ Bhi, const uint32_t* __restrict__ Blo,
    const float* __restrict__ bias, float* __restrict__ out, int rows)
{
    __shared__ uint32_t sHhi[128 * 36];
    __shared__ uint32_t sHlo[128 * 36];

    int tid = threadIdx.x;
    int wid = tid >> 5, lane = tid & 31;
    int g = lane >> 2, tg = lane & 3;
    int r0 = blockIdx.x * 128;

    // load + hi/lo split; each iter covers one row's 8-k chunk
    for (int i = tid; i < 1024; i += 256) {
        int r = i >> 3, k8 = i & 7;
        int gr = r0 + r;
        float4 p0 = make_float4(0.f, 0.f, 0.f, 0.f), p1 = p0;
        if (gr < rows) {
            long s = GATHER ? (long)__ldg(gth + gr) : (long)gr;
            const float4* Pr = (const float4*)(src + s * 64) + k8 * 2;
            p0 = __ldg(Pr); p1 = __ldg(Pr + 1);
        }
        float h[8] = {p0.x, p0.y, p0.z, p0.w, p1.x, p1.y, p1.z, p1.w};
        uint32_t hi[4], lo[4];
#pragma unroll
        for (int j = 0; j < 4; j++) {
            unsigned short a = f2bf(h[2 * j]), b = f2bf(h[2 * j + 1]);
            hi[j] = (uint32_t)a | ((uint32_t)b << 16);
            lo[j] = bfpack(h[2 * j] - bf2f(a), h[2 * j + 1] - bf2f(b));
        }
        int base = r * 36 + k8 * 4;
        *(uint4*)(sHhi + base) = make_uint4(hi[0], hi[1], hi[2], hi[3]);
        *(uint4*)(sHlo + base) = make_uint4(lo[0], lo[1], lo[2], lo[3]);
    }
    __syncthreads();

    int rb = wid * 16;
    uint32_t ahi[4][4], alo[4][4];
    load_afrag(sHhi, sHlo, rb, g, tg, ahi, alo);

#pragma unroll
    for (int nt = 0; nt < 8; nt++) {
        float acc[4] = {0.f, 0.f, 0.f, 0.f};
        mma_hilo_ntile(acc, ahi, alo, Bhi, Blo, nt, lane);
        int c0 = nt * 8 + tg * 2;
        float a0 = 0.f, a1 = 0.f;
        if (BIAS) { a0 = __ldg(bias + c0); a1 = __ldg(bias + c0 + 1); }
        int row0 = r0 + rb + g, row1 = row0 + 8;
        if (row0 < rows) {
            float2 o = make_float2(acc[0] + a0, acc[1] + a1);
            *(float2*)(out + (size_t)row0 * 64 + c0) = o;
        }
        if (row1 < rows) {
            float2 o = make_float2(acc[2] + a0, acc[3] + a1);
            *(float2*)(out + (size_t)row1 * 64 + c0) = o;
        }
    }
}

// ============================================================
// edge_mlp_mma: per 128-edge tile
//   h = relu(P[nb]+Q[sg]) -> bf16 hi/lo tiles in smem (pitch 36 words/row)
//   D = Ah*Bh + Al*Bh + Ah*Bl via mma.sync (HMMA), fp32 accum
//   epilogue: relu(D+b2).w3, 4-lane reduce, exp -> g_ex
// ============================================================
__global__ void __launch_bounds__(256) edge_mlp_mma(
    const int* __restrict__ neigh, const int* __restrict__ seg,
    const float* __restrict__ b2, const float* __restrict__ w3,
    const float* __restrict__ b3)
{
    __shared__ uint32_t sHhi[128 * 36];
    __shared__ uint32_t sHlo[128 * 36];
    __shared__ int sIdx[256];

    int tid = threadIdx.x;
    int wid = tid >> 5, lane = tid & 31;
    int g = lane >> 2, tg = lane & 3;
    int e0 = blockIdx.x * 128;

    if (tid < 128) {
        sIdx[tid]       = __ldg(neigh + e0 + tid);
        sIdx[128 + tid] = __ldg(seg   + e0 + tid);
    }
    __syncthreads();

    for (int i = tid; i < 1024; i += 256) {
        int r = i >> 3, k8 = i & 7;
        const float4* Pr = (const float4*)(g_P + (size_t)sIdx[r] * 64) + k8 * 2;
        const float4* Qr = (const float4*)(g_Q + (size_t)sIdx[128 + r] * 64) + k8 * 2;
        float4 p0 = __ldg(Pr), p1 = __ldg(Pr + 1);
        float4 q0 = __ldg(Qr), q1 = __ldg(Qr + 1);
        float h[8];
        h[0] = fmaxf(p0.x + q0.x, 0.f); h[1] = fmaxf(p0.y + q0.y, 0.f);
        h[2] = fmaxf(p0.z + q0.z, 0.f); h[3] = fmaxf(p0.w + q0.w, 0.f);
        h[4] = fmaxf(p1.x + q1.x, 0.f); h[5] = fmaxf(p1.y + q1.y, 0.f);
        h[6] = fmaxf(p1.z + q1.z, 0.f); h[7] = fmaxf(p1.w + q1.w, 0.f);
        uint32_t hi[4], lo[4];
#pragma unroll
        for (int j = 0; j < 4; j++) {
            unsigned short a = f2bf(h[2 * j]), b = f2bf(h[2 * j + 1]);
            hi[j] = (uint32_t)a | ((uint32_t)b << 16);
            lo[j] = bfpack(h[2 * j] - bf2f(a), h[2 * j + 1] - bf2f(b));
        }
        int base = r * 36 + k8 * 4;
        *(uint4*)(sHhi + base) = make_uint4(hi[0], hi[1], hi[2], hi[3]);
        *(uint4*)(sHlo + base) = make_uint4(lo[0], lo[1], lo[2], lo[3]);
    }
    __syncthreads();

    int rb = wid * 16;
    uint32_t ahi[4][4], alo[4][4];
    load_afrag(sHhi, sHlo, rb, g, tg, ahi, alo);

    float s0 = 0.f, s1 = 0.f;
#pragma unroll
    for (int nt = 0; nt < 8; nt++) {
        float acc[4] = {0.f, 0.f, 0.f, 0.f};
        mma_hilo_ntile(acc, ahi, alo, g_Bfhi, g_Bflo, nt, lane);
        int c0 = nt * 8 + tg * 2, c1 = c0 + 1;
        float bb0 = __ldg(b2 + c0), bb1 = __ldg(b2 + c1);
        float ww0 = __ldg(w3 + c0), ww1 = __ldg(w3 + c1);
        s0 += fmaxf(acc[0] + bb0, 0.f) * ww0 + fmaxf(acc[1] + bb1, 0.f) * ww1;
        s1 += fmaxf(acc[2] + bb0, 0.f) * ww0 + fmaxf(acc[3] + bb1, 0.f) * ww1;
    }
    s0 += __shfl_xor_sync(0xffffffffu, s0, 1);
    s0 += __shfl_xor_sync(0xffffffffu, s0, 2);
    s1 += __shfl_xor_sync(0xffffffffu, s1, 1);
    s1 += __shfl_xor_sync(0xffffffffu, s1, 2);
    if (tg == 0) {
        float b3v = __ldg(b3);
        g_ex[e0 + rb + g]     = expf(s0 + b3v);
        g_ex[e0 + rb + g + 8] = expf(s1 + b3v);
    }
}

// ============================================================
// agg: one warp per node — inline rowptr binary search, softmax denom,
// weighted neighbor sum with half-warp float4 lanes (2 edges in flight).
// ============================================================
__global__ void __launch_bounds__(256) agg_k(
    const int* __restrict__ nodes, const int* __restrict__ neigh,
    const int* __restrict__ seg, const float* __restrict__ u2e,
    float* __restrict__ out)
{
    int w = (blockIdx.x * 256 + threadIdx.x) >> 5;
    int lane = threadIdx.x & 31;
    if (w >= NN) return;
    int half = lane >> 4, l16 = lane & 15;

    // inline lower_bound: lanes 0-15 search w, lanes 16-31 search w+1
    int target = w + half;
    int lo = 0, hi = EE;
    while (lo < hi) {
        int mid = (lo + hi) >> 1;
        if (__ldg(seg + mid) < target) lo = mid + 1; else hi = mid;
    }
    int s = __shfl_sync(0xffffffffu, lo, 0);
    int t = __shfl_sync(0xffffffffu, lo, 16);

    if (s == t) {  // no neighbors: own embedding
        int u = __ldg(nodes + w);
        if (half == 0) {
            float4 v = __ldg((const float4*)(u2e + (size_t)u * 64) + l16);
            *((float4*)(out + (size_t)w * 64) + l16) = v;
        }
        return;
    }

    float d = 0.f;
    for (int e = s + lane; e < t; e += 32) d += __ldg(g_ex + e);
#pragma unroll
    for (int m = 16; m; m >>= 1) d += __shfl_xor_sync(0xffffffffu, d, m);
    float inv = 1.f / d;

    // accumulate: half-warp h handles edges e+h, e+2+h; lane holds 4 dims
    float4 a = make_float4(0.f, 0.f, 0.f, 0.f);
    int e = s;
    for (; e + 4 <= t; e += 4) {
        int   ea = e + half,      eb = e + 2 + half;
        int   na = __ldg(neigh + ea), nb = __ldg(neigh + eb);
        float wa = __ldg(g_ex + ea) * inv, wb = __ldg(g_ex + eb) * inv;
        float4 va = __ldg((const float4*)(u2e + (size_t)na * 64) + l16);
        float4 vb = __ldg((const float4*)(u2e + (size_t)nb * 64) + l16);
        a.x = fmaf(wa, va.x, fmaf(wb, vb.x, a.x));
        a.y = fmaf(wa, va.y, fmaf(wb, vb.y, a.y));
        a.z = fmaf(wa, va.z, fmaf(wb, vb.z, a.z));
        a.w = fmaf(wa, va.w, fmaf(wb, vb.w, a.w));
    }
    for (; e < t; e += 2) {
        int ee = e + half;
        if (ee < t) {
            int   n0 = __ldg(neigh + ee);
            float w0 = __ldg(g_ex + ee) * inv;
            float4 v = __ldg((const float4*)(u2e + (size_t)n0 * 64) + l16);
            a.x = fmaf(w0, v.x, a.x); a.y = fmaf(w0, v.y, a.y);
            a.z = fmaf(w0, v.z, a.z); a.w = fmaf(w0, v.w, a.w);
        }
    }
    a.x += __shfl_xor_sync(0xffffffffu, a.x, 16);
    a.y += __shfl_xor_sync(0xffffffffu, a.y, 16);
    a.z += __shfl_xor_sync(0xffffffffu, a.z, 16);
    a.w += __shfl_xor_sync(0xffffffffu, a.w, 16);
    if (half == 0)
        *((float4*)(out + (size_t)w * 64) + l16) = a;
}

// ============================================================
extern "C" void kernel_launch(void* const* d_in, const int* in_sizes, int n_in,
                              void* d_out, int out_size)
{
    const int*   nodes = (const int*)d_in[0];
    const int*   neigh = (const int*)d_in[1];
    const int*   seg   = (const int*)d_in[2];
    const float* u2e   = (const float*)d_in[3];
    const float* W1    = (const float*)d_in[4];
    const float* b1    = (const float*)d_in[5];
    const float* W2    = (const float*)d_in[6];
    const float* b2    = (const float*)d_in[7];
    const float* w3    = (const float*)d_in[8];
    const float* b3    = (const float*)d_in[9];
    float* out = (float*)d_out;

    float *dP, *dQ;
    cudaGetSymbolAddress((void**)&dP, g_P);
    cudaGetSymbolAddress((void**)&dQ, g_Q);
    uint32_t *pW2h, *pW2l, *pW1th, *pW1tl, *pW1bh, *pW1bl;
    cudaGetSymbolAddress((void**)&pW2h,  g_Bfhi);
    cudaGetSymbolAddress((void**)&pW2l,  g_Bflo);
    cudaGetSymbolAddress((void**)&pW1th, g_BW1thi);
    cudaGetSymbolAddress((void**)&pW1tl, g_BW1tlo);
    cudaGetSymbolAddress((void**)&pW1bh, g_BW1bhi);
    cudaGetSymbolAddress((void**)&pW1bl, g_BW1blo);

    // weight packs (fragment order, bf16 hi/lo)
    prep_pack<<<8, 256>>>(W2, pW2h, pW2l);
    prep_pack<<<8, 256>>>(W1, pW1th, pW1tl);
    prep_pack<<<8, 256>>>(W1 + 64 * 64, pW1bh, pW1bl);
    // P = u2e @ W1[:64]
    rowgemm_mma<false, false><<<(UU + 127) / 128, 256>>>(
        u2e, nullptr, pW1th, pW1tl, nullptr, dP, UU);
    // Q = u2e[nodes] @ W1[64:] + b1
    rowgemm_mma<true, true><<<(NN + 127) / 128, 256>>>(
        u2e, nodes, pW1bh, pW1bl, b1, dQ, NN);
    // per-edge MLP -> exp(logit)  (HMMA)
    edge_mlp_mma<<<EE / 128, 256>>>(neigh, seg, b2, w3, b3);
    // segment softmax + weighted aggregation (+ zero-neighbor fallback)
    agg_k<<<(NN * 32 + 255) / 256, 256>>>(nodes, neigh, seg, u2e, out);
}